// round 14
// baseline (speedup 1.0000x reference)
#include <cuda_runtime.h>
#include <cstdint>

// Who2com reduces exactly to: out = bevs (softmax over axis 1 followed by
// sum over axis 1 is identically 1.0; everything upstream only feeds the
// softmax logits). Kernel = 84 MB copy.
//
// Proven optimum (R7, reproduced bit-identically at 27.136 us):
//  - plain LDG.128 loads (every other load form regresses)
//  - STG.256 with L2::evict_last (writebacks deferred off the critical path;
//    the only mechanism with a measured win, -2.1 us)
//  - exact-division geometry, 256 threads/block
// This round: the one unswept knob around that optimum -- block granularity.
// 5120 blocks x 256 threads x 2 vec8/thread (= 2,621,440 exactly) halves the
// work quantum, smoothing the ragged 17.3-wave tail and the per-die DRAM
// imbalance across SMs. Everything else R7-identical.

__global__ __launch_bounds__(256) void who2com_copy_kernel(
    const float4* __restrict__ src, float* __restrict__ dst)
{
    const int nthreads = gridDim.x * blockDim.x;          // 1,310,720
    const int tid = blockIdx.x * blockDim.x + threadIdx.x;

    #pragma unroll
    for (int k = 0; k < 2; k++) {
        const int c = tid + k * nthreads;                 // vec8 index
        // Plain 128-bit loads: the proven fastest read path.
        float4 a = src[2 * c + 0];
        float4 b = src[2 * c + 1];
        // 256-bit store with L2::evict_last: writebacks deferred past the
        // kernel's critical path.
        asm volatile(
            "st.global.L2::evict_last.v8.f32 [%0], "
            "{%1, %2, %3, %4, %5, %6, %7, %8};"
            :: "l"(dst + (size_t)c * 8),
               "f"(a.x), "f"(a.y), "f"(a.z), "f"(a.w),
               "f"(b.x), "f"(b.y), "f"(b.z), "f"(b.w)
            : "memory");
    }
}

extern "C" void kernel_launch(void* const* d_in, const int* in_sizes, int n_in,
                              void* d_out, int out_size)
{
    const float4* src = (const float4*)d_in[0];   // bevs: [1,4,80,256,256] fp32
    float* dst = (float*)d_out;

    // out_size = 20,971,520 floats = 2,621,440 vec8 = 1,310,720 threads * 2.
    const int threads = 256;
    const int blocks = 5120;
    who2com_copy_kernel<<<blocks, threads>>>(src, dst);
}